// round 14
// baseline (speedup 1.0000x reference)
#include <cuda_runtime.h>
#include <cuda_bf16.h>
#include <cuda_fp16.h>
#include <cstdint>

#define NTOT 7200      // B*L
#define NPAD 7296      // 57 * 128
#define CIN  768
#define MIDD 256
#define KTOT 8912
#define KPAD 8960      // 70 * 128
#define KV8  1114      // KTOT/8
#define NSLOT 280      // 70 tiles * 4 warpN slots per row

#define CT (2.0f/0.07f)
#define CE (2.0f/0.01f)
#define CTL2 41.2198884f      // CT * log2(e)
#define CL7  4.85203026f      // 7 * ln(2)
#define ROWB 80        // main gemm smem row stride (64B rows + pad)
#define ROWC 144       // dp smem row stride (128B rows + pad)
#define GSTG 30720     // main gemm per-stage: 3 tiles * 128 rows * 80B
#define DPSTG 46080    // dp per-stage: A 64*144 + B 256*144

// ------------- device scratch -------------
__device__ __half g_znf[NPAD*MIDD];          // fp16 zn (GEMM A)
__device__ float  g_zn32[NPAD*MIDD];         // fp32 zn (argmax repair)
__device__ __half g_ehh[KPAD*MIDD];          // fp16 en hi
__device__ __half g_ehl[KPAD*MIDD];          // fp16 en lo
__device__ __nv_bfloat16 g_xh[NPAD*CIN];
__device__ __nv_bfloat16 g_xl[NPAD*CIN];
__device__ __nv_bfloat16 g_wth[MIDD*CIN];
__device__ __nv_bfloat16 g_wtl[MIDD*CIN];
__device__ float g_en[KTOT*MIDD];
__device__ __half g_eT[(size_t)NTOT*KTOT];
__device__ float4 g_part[(size_t)NTOT*NSLOT];
__device__ unsigned g_sidx[(size_t)NTOT*NSLOT];
__device__ float g_fT[(size_t)NTOT*NSLOT];
__device__ float g_fE[(size_t)NTOT*NSLOT];
__device__ int   g_idx[NTOT];
__device__ int   g_occ[KTOT];
__device__ float g_avgp[KTOT];
__device__ float g_acc[4];

// ------------- helpers -------------
__device__ __forceinline__ float warpReduceSum(float v){
    #pragma unroll
    for(int o=16;o;o>>=1) v += __shfl_xor_sync(0xFFFFFFFFu, v, o);
    return v;
}
__device__ __forceinline__ unsigned fsort(float f){
    unsigned u = __float_as_uint(f);
    return u ^ ((u >> 31) ? 0xFFFFFFFFu : 0x80000000u);
}
__device__ __forceinline__ uint32_t smem_u32(const void* p){
    uint32_t a;
    asm("{ .reg .u64 t; cvta.to.shared.u64 t, %1; cvt.u32.u64 %0, t; }" : "=r"(a) : "l"(p));
    return a;
}
__device__ __forceinline__ void cpa16(uint32_t s, const void* g){
    asm volatile("cp.async.cg.shared.global [%0], [%1], 16;" :: "r"(s), "l"(g));
}
__device__ __forceinline__ void cp_commit(){
    asm volatile("cp.async.commit_group;");
}
template<int N> __device__ __forceinline__ void cp_wait(){
    asm volatile("cp.async.wait_group %0;" :: "n"(N));
}
__device__ __forceinline__ float pow7(float e){
    float e2 = e*e, e4 = e2*e2;
    return e4*e2*e;
}
__device__ __forceinline__ uint32_t ex2_h2(float g0, float g1){
    __half2 gh = __floats2half2_rn(g0, g1);
    uint32_t gu = *(uint32_t*)&gh;
    uint32_t eu;
    asm("ex2.approx.f16x2 %0, %1;" : "=r"(eu) : "r"(gu));
    return eu;
}
#define LDSM4(R, ADDR) \
    asm volatile("ldmatrix.sync.aligned.m8n8.x4.shared.b16 {%0,%1,%2,%3}, [%4];" \
        : "=r"((R)[0]), "=r"((R)[1]), "=r"((R)[2]), "=r"((R)[3]) : "r"(ADDR))
#define MMA16816(D, A, B0, B1) \
    asm volatile("mma.sync.aligned.m16n8k16.row.col.f32.bf16.bf16.f32 " \
        "{%0,%1,%2,%3},{%4,%5,%6,%7},{%8,%9},{%0,%1,%2,%3};" \
        : "+f"((D)[0]), "+f"((D)[1]), "+f"((D)[2]), "+f"((D)[3]) \
        : "r"((A)[0]), "r"((A)[1]), "r"((A)[2]), "r"((A)[3]), "r"(B0), "r"(B1))
#define MMA16816H(D, A, B0, B1) \
    asm volatile("mma.sync.aligned.m16n8k16.row.col.f32.f16.f16.f32 " \
        "{%0,%1,%2,%3},{%4,%5,%6,%7},{%8,%9},{%0,%1,%2,%3};" \
        : "+f"((D)[0]), "+f"((D)[1]), "+f"((D)[2]), "+f"((D)[3]) \
        : "r"((A)[0]), "r"((A)[1]), "r"((A)[2]), "r"((A)[3]), "r"(B0), "r"(B1))

__device__ __forceinline__ void bsplit(float v, __nv_bfloat16& h, __nv_bfloat16& l){
    h = __float2bfloat16(v);
    l = __float2bfloat16(v - __bfloat162float(h));
}

// ------------- K1: normalize embedding + fp16 split + init scratch ------------
__global__ void norm_emb(const float* __restrict__ emb){
    int k = blockIdx.x, m = threadIdx.x;
    float v = emb[k*MIDD + m];
    float s = warpReduceSum(v*v);
    __shared__ float sm[8];
    if((m & 31) == 0) sm[m>>5] = s;
    __syncthreads();
    if(m == 0){
        float t = 0.f;
        #pragma unroll
        for(int i=0;i<8;i++) t += sm[i];
        sm[0] = 1.f / fmaxf(sqrtf(t), 1e-12f);
        g_avgp[k] = 0.f;
        g_occ[k] = 0;
        if(k < 4) g_acc[k] = 0.f;
    }
    __syncthreads();
    float nv = v * sm[0];
    g_en[k*MIDD + m] = nv;
    __half h = __float2half_rn(nv);
    g_ehh[k*MIDD + m] = h;
    g_ehl[k*MIDD + m] = __float2half_rn(nv - __half2float(h));
}

// ------------- K1a: split x into bf16 hi/lo -------------
__global__ void split_x(const float* __restrict__ x){
    int i = blockIdx.x*256 + threadIdx.x;
    if(i < NTOT*CIN/4){
        float4 v = ((const float4*)x)[i];
        __nv_bfloat16 h0,l0,h1,l1,h2,l2,h3,l3;
        bsplit(v.x,h0,l0); bsplit(v.y,h1,l1); bsplit(v.z,h2,l2); bsplit(v.w,h3,l3);
        __nv_bfloat162 ha; ha.x=h0; ha.y=h1;
        __nv_bfloat162 hb; hb.x=h2; hb.y=h3;
        __nv_bfloat162 la; la.x=l0; la.y=l1;
        __nv_bfloat162 lb; lb.x=l2; lb.y=l3;
        ((__nv_bfloat162*)g_xh)[i*2]   = ha;
        ((__nv_bfloat162*)g_xh)[i*2+1] = hb;
        ((__nv_bfloat162*)g_xl)[i*2]   = la;
        ((__nv_bfloat162*)g_xl)[i*2+1] = lb;
    }
}

// ------------- K1c: split + transpose W via smem tile -------------
__global__ void split_wt(const float* __restrict__ W){
    __shared__ float tile[64][65];
    int t = threadIdx.x;
    int c0 = blockIdx.x * 64, m0 = blockIdx.y * 64;
    #pragma unroll
    for(int i=0;i<16;i++){
        int idx = t + i*256;
        int r = idx >> 6, cc = idx & 63;
        tile[r][cc] = W[(size_t)(c0 + r)*MIDD + m0 + cc];
    }
    __syncthreads();
    #pragma unroll
    for(int i=0;i<16;i++){
        int idx = t + i*256;
        int rm = idx >> 6, cc = idx & 63;
        float v = tile[cc][rm];
        __nv_bfloat16 h, l;
        bsplit(v, h, l);
        size_t o = (size_t)(m0 + rm)*CIN + c0 + cc;
        g_wth[o] = h;
        g_wtl[o] = l;
    }
}

// ------------- K2a: down-projection, 512 threads (16 warps), 4-stage ---------
__global__ __launch_bounds__(512) void dp_mma(const float* __restrict__ bias){
    extern __shared__ char smem[];
    __shared__ float bsh[MIDD];
    __shared__ float spart[64][8];
    __shared__ float rnorm[64];
    int t = threadIdx.x, lane = t & 31, w = t >> 5;
    int rowBase = blockIdx.x * 64;
    int wm = (w & 1) * 32, wn = (w >> 1) * 32;   // 2 M-groups x 8 N-groups
    if(t < MIDD) bsh[t] = bias[t];

    const __nv_bfloat16* Asrc[3] = {g_xh, g_xh, g_xl};
    const __nv_bfloat16* Bsrc[3] = {g_wth, g_wtl, g_wth};

    int ar = t >> 3, au = t & 7;        // 64 rows x 8 units of 16B
    uint32_t sbase = smem_u32(smem);

    int arow = wm + ((lane >> 3) & 1) * 8 + (lane & 7);
    int acol = (lane >> 4) * 8;
    uint32_t aoff = arow*ROWC + acol*2;
    int brow = wn + (lane >> 4) * 8 + (lane & 7);
    int bcol = ((lane >> 3) & 1) * 8;
    uint32_t boff = brow*ROWC + bcol*2;

    float acc[2][4][4];
    #pragma unroll
    for(int i=0;i<2;i++)
        #pragma unroll
        for(int j=0;j<4;j++)
            #pragma unroll
            for(int q=0;q<4;q++) acc[i][j][q] = 0.f;

    auto issue = [&](int c, int buf){
        int p = c / 12;
        int ko = (c % 12) * 64;
        uint32_t s0 = sbase + buf*DPSTG;
        // A: 64 rows x 128B, 512 threads -> exactly one 16B unit each
        cpa16(s0 + ar*ROWC + au*16,
              Asrc[p] + (size_t)(rowBase + ar)*CIN + ko + au*8);
        // B: 256 rows x 128B -> 4 iterations
        const __nv_bfloat16* B0 = Bsrc[p];
        #pragma unroll
        for(int it=0; it<4; it++){
            int r = ar + it*64;
            cpa16(s0 + 9216 + r*ROWC + au*16,
                  B0 + (size_t)r*CIN + ko + au*8);
        }
        cp_commit();
    };

    issue(0,0); issue(1,1); issue(2,2);
    for(int c=0; c<36; c++){
        if(c < 34) cp_wait<2>();
        else if(c == 34) cp_wait<1>();
        else cp_wait<0>();
        __syncthreads();
        if(c+3 < 36) issue(c+3, (c+3)&3);
        int buf = c & 3;
        uint32_t bA = sbase + buf*DPSTG + aoff;
        uint32_t bB = sbase + buf*DPSTG + 9216 + boff;
        #pragma unroll
        for(int s=0;s<4;s++){
            uint32_t Af[2][4];
            #pragma unroll
            for(int i=0;i<2;i++) LDSM4(Af[i], bA + i*(16*ROWC) + s*32);
            uint32_t Bf[2][4];
            #pragma unroll
            for(int jp=0;jp<2;jp++) LDSM4(Bf[jp], bB + jp*(16*ROWC) + s*32);
            #pragma unroll
            for(int i=0;i<2;i++)
                #pragma unroll
                for(int j=0;j<4;j++)
                    MMA16816(acc[i][j], Af[i], Bf[j>>1][(j&1)*2], Bf[j>>1][(j&1)*2+1]);
        }
    }
    __syncthreads();

    #pragma unroll
    for(int i=0;i<2;i++)
        #pragma unroll
        for(int j=0;j<4;j++){
            int col = wn + j*8 + (lane & 3)*2;
            acc[i][j][0] += bsh[col];   acc[i][j][1] += bsh[col+1];
            acc[i][j][2] += bsh[col];   acc[i][j][3] += bsh[col+1];
        }
    #pragma unroll
    for(int i=0;i<2;i++)
        #pragma unroll
        for(int h=0;h<2;h++){
            float s = 0.f;
            #pragma unroll
            for(int j=0;j<4;j++){
                float v0 = acc[i][j][h*2], v1 = acc[i][j][h*2+1];
                s += v0*v0 + v1*v1;
            }
            s += __shfl_xor_sync(0xFFFFFFFFu, s, 1);
            s += __shfl_xor_sync(0xFFFFFFFFu, s, 2);
            if((lane & 3) == 0)
                spart[wm + i*16 + h*8 + (lane>>2)][w>>1] = s;
        }
    __syncthreads();
    if(t < 64){
        float ss = 0.f;
        #pragma unroll
        for(int q=0;q<8;q++) ss += spart[t][q];
        rnorm[t] = 1.f / fmaxf(sqrtf(ss), 1e-12f);
    }
    __syncthreads();
    #pragma unroll
    for(int i=0;i<2;i++)
        #pragma unroll
        for(int h=0;h<2;h++){
            int rl = wm + i*16 + h*8 + (lane>>2);
            float rs = rnorm[rl];
            size_t row = rowBase + rl;
            #pragma unroll
            for(int j=0;j<4;j++){
                int col = wn + j*8 + (lane & 3)*2;
                float v0 = acc[i][j][h*2] * rs, v1 = acc[i][j][h*2+1] * rs;
                __half2 hv = __floats2half2_rn(v0, v1);
                *(__half2*)&g_znf[row*MIDD + col] = hv;
                float2 fv; fv.x = v0; fv.y = v1;
                *(float2*)&g_zn32[row*MIDD + col] = fv;
            }
        }
}

// ------------- K2: main GEMM — fp16 2-product, ex2.f16x2 epilogue ------------
__global__ __launch_bounds__(256, 2) void gemm_mma(){
    extern __shared__ char smem[];
    int t = threadIdx.x;
    int lane = t & 31, w = t >> 5;
    int rowBase = blockIdx.y * 128;
    int colBase = blockIdx.x * 128;

    uint32_t sbase = smem_u32(smem);

    int wm = (w & 1) * 64, wn = (w >> 1) * 32;
    int arow = wm + ((lane >> 3) & 1) * 8 + (lane & 7);
    int acol = (lane >> 4) * 8;
    uint32_t aoff = arow*ROWB + acol*2;
    int brow = wn + (lane >> 4) * 8 + (lane & 7);
    int bcol = ((lane >> 3) & 1) * 8;
    uint32_t boff = brow*ROWB + bcol*2;

    float acc[4][4][4];
    #pragma unroll
    for(int i=0;i<4;i++)
        #pragma unroll
        for(int j=0;j<4;j++)
            #pragma unroll
            for(int q=0;q<4;q++) acc[i][j][q] = 0.f;

    int lr4 = t >> 2, lu4 = t & 3;
    auto issue = [&](int c, int stg){
        int ko = c * 32;
        uint32_t s0 = sbase + stg*GSTG;
        #pragma unroll
        for(int rep=0; rep<2; rep++){
            int r = lr4 + rep*64;
            uint32_t so = r*ROWB + lu4*16;
            cpa16(s0 +         so, g_znf + (size_t)(rowBase + r)*MIDD + ko + lu4*8);
            cpa16(s0 + 10240 + so, g_ehh + (size_t)(colBase + r)*MIDD + ko + lu4*8);
            cpa16(s0 + 20480 + so, g_ehl + (size_t)(colBase + r)*MIDD + ko + lu4*8);
        }
        cp_commit();
    };

    issue(0,0); issue(1,1);
    for(int c=0; c<8; c++){
        if(c < 7) cp_wait<1>();
        else cp_wait<0>();
        __syncthreads();
        if(c+2 < 8) issue(c+2, (c+2)%3);
        uint32_t base = sbase + (c%3)*GSTG;
        #pragma unroll
        for(int s=0;s<2;s++){
            uint32_t Af[4][4];
            #pragma unroll
            for(int i=0;i<4;i++) LDSM4(Af[i], base + aoff + i*(16*ROWB) + s*32);
            uint32_t Bh_[2][4];
            #pragma unroll
            for(int jp=0;jp<2;jp++) LDSM4(Bh_[jp], base + 10240 + boff + jp*(16*ROWB) + s*32);
            #pragma unroll
            for(int i=0;i<4;i++)
                #pragma unroll
                for(int j=0;j<4;j++)
                    MMA16816H(acc[i][j], Af[i], Bh_[j>>1][(j&1)*2], Bh_[j>>1][(j&1)*2+1]);
            uint32_t Bl_[2][4];
            #pragma unroll
            for(int jp=0;jp<2;jp++) LDSM4(Bl_[jp], base + 20480 + boff + jp*(16*ROWB) + s*32);
            #pragma unroll
            for(int i=0;i<4;i++)
                #pragma unroll
                for(int j=0;j<4;j++)
                    MMA16816H(acc[i][j], Af[i], Bl_[j>>1][(j&1)*2], Bl_[j>>1][(j&1)*2+1]);
        }
    }

    // epilogue: slot max/argmax -> eT via ex2.f16x2 + softmax partials
    #pragma unroll
    for(int i=0;i<4;i++){
        #pragma unroll
        for(int h=0;h<2;h++){
            int rl = wm + i*16 + h*8 + (lane >> 2);
            int row = rowBase + rl;
            bool rok = row < NTOT;
            float v[8];
            float best = -1e30f; int bc = 0;
            #pragma unroll
            for(int j=0;j<4;j++){
                int col = colBase + wn + j*8 + (lane & 3)*2;
                float v0 = acc[i][j][h*2+0];
                float v1 = acc[i][j][h*2+1];
                bool cv = col < KTOT;
                if(cv){
                    if(v0 > best){ best = v0; bc = col; }
                    if(v1 > best){ best = v1; bc = col+1; }
                }
                v[j*2]   = cv ? v0 : -1e4f;
                v[j*2+1] = cv ? v1 : -1e4f;
            }
            float m = v[0];
            #pragma unroll
            for(int q=1;q<8;q++) m = fmaxf(m, v[q]);
            m = fmaxf(m, __shfl_xor_sync(0xFFFFFFFFu, m, 1));
            m = fmaxf(m, __shfl_xor_sync(0xFFFFFFFFu, m, 2));
            uint32_t eTh[4];
            float st=0.f, se=0.f, te=0.f;
            #pragma unroll
            for(int q=0;q<8;q+=2){
                float g0 = CTL2 * (v[q]   - m);
                float g1 = CTL2 * (v[q+1] - m);
                uint32_t eu = ex2_h2(g0, g1);
                eTh[q>>1] = eu;
                __half2 eh2 = *(__half2*)&eu;
                float2 ef = __half22float2(eh2);
                st += ef.x + ef.y;
                float e7a = pow7(ef.x), e7b = pow7(ef.y);
                se += e7a + e7b;
                te += e7a*(CL7*g0) + e7b*(CL7*g1);
            }
            if(rok){
                __half* erow = g_eT + (size_t)row * KTOT;
                #pragma unroll
                for(int j=0;j<4;j++){
                    int col = colBase + wn + j*8 + (lane & 3)*2;
                    if(col < KTOT)
                        *(uint32_t*)(erow + col) = eTh[j];
                }
            }
            st += __shfl_xor_sync(0xFFFFFFFFu, st, 1);
            st += __shfl_xor_sync(0xFFFFFFFFu, st, 2);
            se += __shfl_xor_sync(0xFFFFFFFFu, se, 1);
            se += __shfl_xor_sync(0xFFFFFFFFu, se, 2);
            te += __shfl_xor_sync(0xFFFFFFFFu, te, 1);
            te += __shfl_xor_sync(0xFFFFFFFFu, te, 2);
            unsigned long long key =
                (((unsigned long long)fsort(best)) << 32) |
                (unsigned long long)(0xFFFFFFFFu - (unsigned)bc);
            {
                unsigned long long o1 = __shfl_xor_sync(0xFFFFFFFFu, key, 1);
                if(o1 > key) key = o1;
                unsigned long long o2 = __shfl_xor_sync(0xFFFFFFFFu, key, 2);
                if(o2 > key) key = o2;
            }
            if((lane & 3) == 0 && rok){
                size_t slotIdx = (size_t)row*NSLOT + blockIdx.x*4 + (w>>1);
                float4 p4; p4.x = m; p4.y = st; p4.z = se; p4.w = te;
                g_part[slotIdx] = p4;
                g_sidx[slotIdx] = 0xFFFFFFFFu - (unsigned)(key & 0xFFFFFFFFull);
            }
        }
    }
}

// ------------- K3: combine partials + scale factors + exact argmax repair -----
__global__ void combine(){
    int t = threadIdx.x;
    int row = blockIdx.x*8 + (t>>5);
    int lane = t & 31;
    if(row >= NTOT) return;
    const float4* P = g_part + (size_t)row*NSLOT;
    float m = -1e30f, st = 0.f, se = 0.f, te = 0.f;
    for(int s=lane; s<NSLOT; s+=32){
        float4 p = P[s];
        float M = fmaxf(m, p.x);
        float ca = __expf(CT*(m - M));
        float cb = __expf(CT*(p.x - M));
        float ca7 = pow7(ca), cb7 = pow7(cb);
        st = st*ca + p.y*cb;
        te = (te + CE*(m - M)*se)*ca7 + (p.w + CE*(p.x - M)*p.z)*cb7;
        se = se*ca7 + p.z*cb7;
        m = M;
    }
    #pragma unroll
    for(int off=16; off; off>>=1){
        float om  = __shfl_xor_sync(0xFFFFFFFFu, m,  off);
        float ost = __shfl_xor_sync(0xFFFFFFFFu, st, off);
        float ose = __shfl_xor_sync(0xFFFFFFFFu, se, off);
        float ote = __shfl_xor_sync(0xFFFFFFFFu, te, off);
        float M = fmaxf(m, om);
        float ca = __expf(CT*(m - M));
        float cb = __expf(CT*(om - M));
        float ca7 = pow7(ca), cb7 = pow7(cb);
        st = st*ca + ost*cb;
        te = (te + CE*(m - M)*se)*ca7 + (ote + CE*(om - M)*ose)*cb7;
        se = se*ca7 + ose*cb7;
        m = M;
    }
    float ist = 1.f / st, ise = 1.f / se;
    for(int s=lane; s<NSLOT; s+=32){
        float ms = P[s].x;
        float eT = __expf(CT*(ms - m));
        g_fT[(size_t)row*NSLOT + s] = eT * ist;
        g_fE[(size_t)row*NSLOT + s] = pow7(eT) * ise;
    }
    float thr = m - 3e-4f;
    float bestVal = -1e30f; int bestCol = 0x7FFFFFFF;
    const float4* zr = (const float4*)(g_zn32 + (size_t)row*MIDD);
    for(int s0=0; s0<NSLOT; s0+=32){
        int s = s0 + lane;
        bool c = (s < NSLOT) && (P[s].x >= thr);
        unsigned mk = __ballot_sync(0xFFFFFFFFu, c);
        while(mk){
            int src = __ffs(mk) - 1; mk &= mk - 1;
            int slot = s0 + src;
            int col = (int)g_sidx[(size_t)row*NSLOT + slot];
            float a = 0.f;
            const float4* er = (const float4*)(g_en + (size_t)col*MIDD);
            #pragma unroll 2
            for(int q=lane; q<64; q+=32){
                float4 av = zr[q], bv = er[q];
                a += av.x*bv.x + av.y*bv.y + av.z*bv.z + av.w*bv.w;
            }
            a = warpReduceSum(a);
            if(a > bestVal || (a == bestVal && col < bestCol)){
                bestVal = a; bestCol = col;
            }
        }
    }
    if(lane == 0){
        g_idx[row] = bestCol;
        g_occ[bestCol] = 1;
        atomicAdd(&g_acc[0], 2.f - 2.f*bestVal);
        atomicAdd(&g_acc[1], te/se - logf(se));
    }
}

// ------------- K4: probs + entropy column sums (fp16 eT in, f32 probs out) ----
__global__ void probs_avg(float* __restrict__ Cc){
    int k8 = blockIdx.x*256 + threadIdx.x;
    if(k8 >= KV8) return;
    int slot = k8 >> 2;
    int n0 = blockIdx.y * 50;
    float a[8];
    #pragma unroll
    for(int q=0;q<8;q++) a[q] = 0.f;
    const uint4* E = (const uint4*)g_eT;
    for(int n=n0; n<n0+50; n++){
        float fT = g_fT[(size_t)n*NSLOT + slot];
        float fE = g_fE[(size_t)n*NSLOT + slot];
        uint4 ev = E[(size_t)n*KV8 + k8];
        float2 f0 = __half22float2(*(__half2*)&ev.x);
        float2 f1 = __half22float2(*(__half2*)&ev.y);
        float2 f2 = __half22float2(*(__half2*)&ev.z);
        float2 f3 = __half22float2(*(__half2*)&ev.w);
        float vv[8] = {f0.x,f0.y,f1.x,f1.y,f2.x,f2.y,f3.x,f3.y};
        float4 o0, o1;
        o0.x = vv[0]*fT; o0.y = vv[1]*fT; o0.z = vv[2]*fT; o0.w = vv[3]*fT;
        o1.x = vv[4]*fT; o1.y = vv[5]*fT; o1.z = vv[6]*fT; o1.w = vv[7]*fT;
        #pragma unroll
        for(int q=0;q<8;q++) a[q] += pow7(vv[q]) * fE;
        size_t off = (size_t)n * KTOT + (size_t)k8*8;
        *(float4*)(Cc + off)     = o0;
        *(float4*)(Cc + off + 4) = o1;
    }
    int k = k8*8;
    #pragma unroll
    for(int q=0;q<8;q++) atomicAdd(&g_avgp[k+q], a[q]);
}

// ------------- K5: scalars -------------
__global__ void finalize(float* __restrict__ scal){
    int t = threadIdx.x;
    float cnt = 0.f, s = 0.f;
    for(int k=t; k<KTOT; k+=256){
        cnt += g_occ[k] ? 1.f : 0.f;
        float ap = g_avgp[k] * (1.f/7200.f);
        s += ap * logf(ap + 1e-5f);
    }
    cnt = warpReduceSum(cnt); s = warpReduceSum(s);
    __shared__ float r0[8], r1[8];
    if((t & 31) == 0){ r0[t>>5]=cnt; r1[t>>5]=s; }
    __syncthreads();
    if(t == 0){
        float c=0.f, sl=0.f;
        #pragma unroll
        for(int i=0;i<8;i++){ c+=r0[i]; sl+=r1[i]; }
        float usage = c / (float)KTOT;
        float vq = g_acc[0] / (7200.f * 256.f);
        float sample_entropy = -(g_acc[1] / 7200.f);
        scal[0] = usage;
        scal[1] = vq;
        scal[2] = vq;
        scal[3] = sample_entropy + sl;
    }
}

// ------------- K6: gather z_q_ste -------------
__global__ void gather_zq(float* __restrict__ outz){
    int n = blockIdx.x, m = threadIdx.x;
    outz[(size_t)n*MIDD + m] = g_en[(size_t)g_idx[n]*MIDD + m];
}

// ------------- launch -------------
extern "C" void kernel_launch(void* const* d_in, const int* in_sizes, int n_in,
                              void* d_out, int out_size){
    const float* x   = (const float*)d_in[0];
    const float* W   = (const float*)d_in[1];
    const float* b   = (const float*)d_in[2];
    const float* emb = (const float*)d_in[3];
    float* out = (float*)d_out;
    float* zq = out;
    float* probs = out + (size_t)NTOT*MIDD;
    float* scal  = out + (size_t)NTOT*MIDD + (size_t)NTOT*KTOT;

    cudaFuncSetAttribute(gemm_mma, cudaFuncAttributeMaxDynamicSharedMemorySize, 3*GSTG);
    cudaFuncSetAttribute(dp_mma,   cudaFuncAttributeMaxDynamicSharedMemorySize, 4*DPSTG);

    norm_emb<<<KTOT, 256>>>(emb);
    split_x<<<(NTOT*CIN/4 + 255)/256, 256>>>(x);
    split_wt<<<dim3(CIN/64, MIDD/64), 256>>>(W);
    dp_mma<<<NPAD/64, 512, 4*DPSTG>>>(b);
    gemm_mma<<<dim3(KPAD/128, NPAD/128), 256, 3*GSTG>>>();
    combine<<<NTOT/8, 256>>>();
    probs_avg<<<dim3((KV8+255)/256, 144), 256>>>(probs);
    finalize<<<1, 256>>>(scal);
    gather_zq<<<NTOT, 256>>>(zq);
}

// round 15
// speedup vs baseline: 1.5096x; 1.5096x over previous
#include <cuda_runtime.h>
#include <cuda_bf16.h>
#include <cuda_fp16.h>
#include <cstdint>

#define NTOT 7200      // B*L
#define NPAD 7296      // 57 * 128
#define CIN  768
#define MIDD 256
#define KTOT 8912
#define KPAD 8960      // 70 * 128
#define KV8  1114      // KTOT/8
#define NSLOT 280      // 70 tiles * 4 warpN slots per row

#define CT (2.0f/0.07f)
#define CE (2.0f/0.01f)
#define CTL2 41.2198884f      // CT * log2(e)
#define CL7  4.85203026f      // 7 * ln(2)
#define ROWB 80        // main gemm smem row stride (64B rows + pad)
#define ROWC 144       // dp smem row stride (128B rows + pad)
#define GSTG 30720     // main gemm per-stage: 3 tiles * 128 rows * 80B
#define DPSTG 46080    // dp per-stage: A 64*144 + B 256*144

// ------------- device scratch -------------
__device__ __half g_znf[NPAD*MIDD];          // fp16 zn (GEMM A)
__device__ float  g_zn32[NPAD*MIDD];         // fp32 zn (argmax repair)
__device__ __half g_ehh[KPAD*MIDD];          // fp16 en hi
__device__ __half g_ehl[KPAD*MIDD];          // fp16 en lo
__device__ __nv_bfloat16 g_xh[NPAD*CIN];
__device__ __nv_bfloat16 g_xl[NPAD*CIN];
__device__ __nv_bfloat16 g_wth[MIDD*CIN];
__device__ __nv_bfloat16 g_wtl[MIDD*CIN];
__device__ float g_en[KTOT*MIDD];
__device__ __half g_eT[(size_t)NTOT*KTOT];
__device__ float4 g_part[(size_t)NTOT*NSLOT];
__device__ unsigned g_sidx[(size_t)NTOT*NSLOT];
__device__ float g_fT[(size_t)NTOT*NSLOT];
__device__ float g_fE[(size_t)NTOT*NSLOT];
__device__ int   g_idx[NTOT];
__device__ int   g_occ[KTOT];
__device__ float g_avgp[KTOT];
__device__ float g_acc[4];

// ------------- helpers -------------
__device__ __forceinline__ float warpReduceSum(float v){
    #pragma unroll
    for(int o=16;o;o>>=1) v += __shfl_xor_sync(0xFFFFFFFFu, v, o);
    return v;
}
__device__ __forceinline__ unsigned fsort(float f){
    unsigned u = __float_as_uint(f);
    return u ^ ((u >> 31) ? 0xFFFFFFFFu : 0x80000000u);
}
__device__ __forceinline__ uint32_t smem_u32(const void* p){
    uint32_t a;
    asm("{ .reg .u64 t; cvta.to.shared.u64 t, %1; cvt.u32.u64 %0, t; }" : "=r"(a) : "l"(p));
    return a;
}
__device__ __forceinline__ void cpa16(uint32_t s, const void* g){
    asm volatile("cp.async.cg.shared.global [%0], [%1], 16;" :: "r"(s), "l"(g));
}
__device__ __forceinline__ void cp_commit(){
    asm volatile("cp.async.commit_group;");
}
template<int N> __device__ __forceinline__ void cp_wait(){
    asm volatile("cp.async.wait_group %0;" :: "n"(N));
}
__device__ __forceinline__ float pow7(float e){
    float e2 = e*e, e4 = e2*e2;
    return e4*e2*e;
}
__device__ __forceinline__ uint32_t ex2_h2(float g0, float g1){
    __half2 gh = __floats2half2_rn(g0, g1);
    uint32_t gu = *(uint32_t*)&gh;
    uint32_t eu;
    asm("ex2.approx.f16x2 %0, %1;" : "=r"(eu) : "r"(gu));
    return eu;
}
#define LDSM4(R, ADDR) \
    asm volatile("ldmatrix.sync.aligned.m8n8.x4.shared.b16 {%0,%1,%2,%3}, [%4];" \
        : "=r"((R)[0]), "=r"((R)[1]), "=r"((R)[2]), "=r"((R)[3]) : "r"(ADDR))
#define MMA16816(D, A, B0, B1) \
    asm volatile("mma.sync.aligned.m16n8k16.row.col.f32.bf16.bf16.f32 " \
        "{%0,%1,%2,%3},{%4,%5,%6,%7},{%8,%9},{%0,%1,%2,%3};" \
        : "+f"((D)[0]), "+f"((D)[1]), "+f"((D)[2]), "+f"((D)[3]) \
        : "r"((A)[0]), "r"((A)[1]), "r"((A)[2]), "r"((A)[3]), "r"(B0), "r"(B1))
#define MMA16816H(D, A, B0, B1) \
    asm volatile("mma.sync.aligned.m16n8k16.row.col.f32.f16.f16.f32 " \
        "{%0,%1,%2,%3},{%4,%5,%6,%7},{%8,%9},{%0,%1,%2,%3};" \
        : "+f"((D)[0]), "+f"((D)[1]), "+f"((D)[2]), "+f"((D)[3]) \
        : "r"((A)[0]), "r"((A)[1]), "r"((A)[2]), "r"((A)[3]), "r"(B0), "r"(B1))

__device__ __forceinline__ void bsplit(float v, __nv_bfloat16& h, __nv_bfloat16& l){
    h = __float2bfloat16(v);
    l = __float2bfloat16(v - __bfloat162float(h));
}

// ------------- K1: normalize embedding + fp16 split + init scratch ------------
__global__ void norm_emb(const float* __restrict__ emb){
    int k = blockIdx.x, m = threadIdx.x;
    float v = emb[k*MIDD + m];
    float s = warpReduceSum(v*v);
    __shared__ float sm[8];
    if((m & 31) == 0) sm[m>>5] = s;
    __syncthreads();
    if(m == 0){
        float t = 0.f;
        #pragma unroll
        for(int i=0;i<8;i++) t += sm[i];
        sm[0] = 1.f / fmaxf(sqrtf(t), 1e-12f);
        g_avgp[k] = 0.f;
        g_occ[k] = 0;
        if(k < 4) g_acc[k] = 0.f;
    }
    __syncthreads();
    float nv = v * sm[0];
    g_en[k*MIDD + m] = nv;
    __half h = __float2half_rn(nv);
    g_ehh[k*MIDD + m] = h;
    g_ehl[k*MIDD + m] = __float2half_rn(nv - __half2float(h));
}

// ------------- K1a: split x into bf16 hi/lo -------------
__global__ void split_x(const float* __restrict__ x){
    int i = blockIdx.x*256 + threadIdx.x;
    if(i < NTOT*CIN/4){
        float4 v = ((const float4*)x)[i];
        __nv_bfloat16 h0,l0,h1,l1,h2,l2,h3,l3;
        bsplit(v.x,h0,l0); bsplit(v.y,h1,l1); bsplit(v.z,h2,l2); bsplit(v.w,h3,l3);
        __nv_bfloat162 ha; ha.x=h0; ha.y=h1;
        __nv_bfloat162 hb; hb.x=h2; hb.y=h3;
        __nv_bfloat162 la; la.x=l0; la.y=l1;
        __nv_bfloat162 lb; lb.x=l2; lb.y=l3;
        ((__nv_bfloat162*)g_xh)[i*2]   = ha;
        ((__nv_bfloat162*)g_xh)[i*2+1] = hb;
        ((__nv_bfloat162*)g_xl)[i*2]   = la;
        ((__nv_bfloat162*)g_xl)[i*2+1] = lb;
    }
}

// ------------- K1c: split + transpose W via smem tile -------------
__global__ void split_wt(const float* __restrict__ W){
    __shared__ float tile[64][65];
    int t = threadIdx.x;
    int c0 = blockIdx.x * 64, m0 = blockIdx.y * 64;
    #pragma unroll
    for(int i=0;i<16;i++){
        int idx = t + i*256;
        int r = idx >> 6, cc = idx & 63;
        tile[r][cc] = W[(size_t)(c0 + r)*MIDD + m0 + cc];
    }
    __syncthreads();
    #pragma unroll
    for(int i=0;i<16;i++){
        int idx = t + i*256;
        int rm = idx >> 6, cc = idx & 63;
        float v = tile[cc][rm];
        __nv_bfloat16 h, l;
        bsplit(v, h, l);
        size_t o = (size_t)(m0 + rm)*CIN + c0 + cc;
        g_wth[o] = h;
        g_wtl[o] = l;
    }
}

// ------------- K2a: down-projection, BK=64, 4-stage pipeline (R10/R13 config) -
__global__ __launch_bounds__(256) void dp_mma(const float* __restrict__ bias){
    extern __shared__ char smem[];
    __shared__ float bsh[MIDD];
    __shared__ float spart[64][4];
    __shared__ float rnorm[64];
    int t = threadIdx.x, lane = t & 31, w = t >> 5;
    int rowBase = blockIdx.x * 64;
    int wm = (w & 1) * 32, wn = (w >> 1) * 64;
    bsh[t] = bias[t];

    const __nv_bfloat16* Asrc[3] = {g_xh, g_xh, g_xl};
    const __nv_bfloat16* Bsrc[3] = {g_wth, g_wtl, g_wth};

    int ar = t >> 2, au = t & 3;
    uint32_t sbase = smem_u32(smem);

    int arow = wm + ((lane >> 3) & 1) * 8 + (lane & 7);
    int acol = (lane >> 4) * 8;
    uint32_t aoff = arow*ROWC + acol*2;
    int brow = wn + (lane >> 4) * 8 + (lane & 7);
    int bcol = ((lane >> 3) & 1) * 8;
    uint32_t boff = brow*ROWC + bcol*2;

    float acc[2][8][4];
    #pragma unroll
    for(int i=0;i<2;i++)
        #pragma unroll
        for(int j=0;j<8;j++)
            #pragma unroll
            for(int q=0;q<4;q++) acc[i][j][q] = 0.f;

    auto issue = [&](int c, int buf){
        int p = c / 12;
        int ko = (c % 12) * 64;
        uint32_t s0 = sbase + buf*DPSTG;
        const __nv_bfloat16* As = Asrc[p] + (size_t)(rowBase + ar)*CIN + ko + au*16;
        cpa16(s0 + ar*ROWC + au*32,      As);
        cpa16(s0 + ar*ROWC + au*32 + 16, As + 8);
        const __nv_bfloat16* B0 = Bsrc[p];
        #pragma unroll
        for(int it=0; it<4; it++){
            int r = ar + it*64;
            const __nv_bfloat16* Bs = B0 + (size_t)r*CIN + ko + au*16;
            cpa16(s0 + 9216 + r*ROWC + au*32,      Bs);
            cpa16(s0 + 9216 + r*ROWC + au*32 + 16, Bs + 8);
        }
        cp_commit();
    };

    issue(0,0); issue(1,1); issue(2,2);
    for(int c=0; c<36; c++){
        if(c < 34) cp_wait<2>();
        else if(c == 34) cp_wait<1>();
        else cp_wait<0>();
        __syncthreads();
        if(c+3 < 36) issue(c+3, (c+3)&3);
        int buf = c & 3;
        uint32_t bA = sbase + buf*DPSTG + aoff;
        uint32_t bB = sbase + buf*DPSTG + 9216 + boff;
        #pragma unroll
        for(int s=0;s<4;s++){
            uint32_t Af[2][4];
            #pragma unroll
            for(int i=0;i<2;i++) LDSM4(Af[i], bA + i*(16*ROWC) + s*32);
            uint32_t Bf[4][4];
            #pragma unroll
            for(int jp=0;jp<4;jp++) LDSM4(Bf[jp], bB + jp*(16*ROWC) + s*32);
            #pragma unroll
            for(int i=0;i<2;i++)
                #pragma unroll
                for(int j=0;j<8;j++)
                    MMA16816(acc[i][j], Af[i], Bf[j>>1][(j&1)*2], Bf[j>>1][(j&1)*2+1]);
        }
    }
    __syncthreads();

    #pragma unroll
    for(int i=0;i<2;i++)
        #pragma unroll
        for(int j=0;j<8;j++){
            int col = wn + j*8 + (lane & 3)*2;
            acc[i][j][0] += bsh[col];   acc[i][j][1] += bsh[col+1];
            acc[i][j][2] += bsh[col];   acc[i][j][3] += bsh[col+1];
        }
    #pragma unroll
    for(int i=0;i<2;i++)
        #pragma unroll
        for(int h=0;h<2;h++){
            float s = 0.f;
            #pragma unroll
            for(int j=0;j<8;j++){
                float v0 = acc[i][j][h*2], v1 = acc[i][j][h*2+1];
                s += v0*v0 + v1*v1;
            }
            s += __shfl_xor_sync(0xFFFFFFFFu, s, 1);
            s += __shfl_xor_sync(0xFFFFFFFFu, s, 2);
            if((lane & 3) == 0)
                spart[wm + i*16 + h*8 + (lane>>2)][w>>1] = s;
        }
    __syncthreads();
    if(t < 64){
        float ss = spart[t][0] + spart[t][1] + spart[t][2] + spart[t][3];
        rnorm[t] = 1.f / fmaxf(sqrtf(ss), 1e-12f);
    }
    __syncthreads();
    #pragma unroll
    for(int i=0;i<2;i++)
        #pragma unroll
        for(int h=0;h<2;h++){
            int rl = wm + i*16 + h*8 + (lane>>2);
            float rs = rnorm[rl];
            size_t row = rowBase + rl;
            #pragma unroll
            for(int j=0;j<8;j++){
                int col = wn + j*8 + (lane & 3)*2;
                float v0 = acc[i][j][h*2] * rs, v1 = acc[i][j][h*2+1] * rs;
                __half2 hv = __floats2half2_rn(v0, v1);
                *(__half2*)&g_znf[row*MIDD + col] = hv;
                float2 fv; fv.x = v0; fv.y = v1;
                *(float2*)&g_zn32[row*MIDD + col] = fv;
            }
        }
}

// ------------- K2: main GEMM — fp16 2-product, ex2.f16x2 epilogue ------------
__global__ __launch_bounds__(256, 2) void gemm_mma(){
    extern __shared__ char smem[];
    int t = threadIdx.x;
    int lane = t & 31, w = t >> 5;
    int rowBase = blockIdx.y * 128;
    int colBase = blockIdx.x * 128;

    uint32_t sbase = smem_u32(smem);

    int wm = (w & 1) * 64, wn = (w >> 1) * 32;
    int arow = wm + ((lane >> 3) & 1) * 8 + (lane & 7);
    int acol = (lane >> 4) * 8;
    uint32_t aoff = arow*ROWB + acol*2;
    int brow = wn + (lane >> 4) * 8 + (lane & 7);
    int bcol = ((lane >> 3) & 1) * 8;
    uint32_t boff = brow*ROWB + bcol*2;

    float acc[4][4][4];
    #pragma unroll
    for(int i=0;i<4;i++)
        #pragma unroll
        for(int j=0;j<4;j++)
            #pragma unroll
            for(int q=0;q<4;q++) acc[i][j][q] = 0.f;

    int lr4 = t >> 2, lu4 = t & 3;
    auto issue = [&](int c, int stg){
        int ko = c * 32;
        uint32_t s0 = sbase + stg*GSTG;
        #pragma unroll
        for(int rep=0; rep<2; rep++){
            int r = lr4 + rep*64;
            uint32_t so = r*ROWB + lu4*16;
            cpa16(s0 +         so, g_znf + (size_t)(rowBase + r)*MIDD + ko + lu4*8);
            cpa16(s0 + 10240 + so, g_ehh + (size_t)(colBase + r)*MIDD + ko + lu4*8);
            cpa16(s0 + 20480 + so, g_ehl + (size_t)(colBase + r)*MIDD + ko + lu4*8);
        }
        cp_commit();
    };

    issue(0,0); issue(1,1);
    for(int c=0; c<8; c++){
        if(c < 7) cp_wait<1>();
        else cp_wait<0>();
        __syncthreads();
        if(c+2 < 8) issue(c+2, (c+2)%3);
        uint32_t base = sbase + (c%3)*GSTG;
        #pragma unroll
        for(int s=0;s<2;s++){
            uint32_t Af[4][4];
            #pragma unroll
            for(int i=0;i<4;i++) LDSM4(Af[i], base + aoff + i*(16*ROWB) + s*32);
            uint32_t Bh_[2][4];
            #pragma unroll
            for(int jp=0;jp<2;jp++) LDSM4(Bh_[jp], base + 10240 + boff + jp*(16*ROWB) + s*32);
            #pragma unroll
            for(int i=0;i<4;i++)
                #pragma unroll
                for(int j=0;j<4;j++)
                    MMA16816H(acc[i][j], Af[i], Bh_[j>>1][(j&1)*2], Bh_[j>>1][(j&1)*2+1]);
            uint32_t Bl_[2][4];
            #pragma unroll
            for(int jp=0;jp<2;jp++) LDSM4(Bl_[jp], base + 20480 + boff + jp*(16*ROWB) + s*32);
            #pragma unroll
            for(int i=0;i<4;i++)
                #pragma unroll
                for(int j=0;j<4;j++)
                    MMA16816H(acc[i][j], Af[i], Bl_[j>>1][(j&1)*2], Bl_[j>>1][(j&1)*2+1]);
        }
    }

    // epilogue: slot max/argmax -> eT via ex2.f16x2 + softmax partials
    #pragma unroll
    for(int i=0;i<4;i++){
        #pragma unroll
        for(int h=0;h<2;h++){
            int rl = wm + i*16 + h*8 + (lane >> 2);
            int row = rowBase + rl;
            bool rok = row < NTOT;
            float v[8];
            float best = -1e30f; int bc = 0;
            #pragma unroll
            for(int j=0;j<4;j++){
                int col = colBase + wn + j*8 + (lane & 3)*2;
                float v0 = acc[i][j][h*2+0];
                float v1 = acc[i][j][h*2+1];
                bool cv = col < KTOT;
                if(cv){
                    if(v0 > best){ best = v0; bc = col; }
                    if(v1 > best){ best = v1; bc = col+1; }
                }
                v[j*2]   = cv ? v0 : -1e4f;
                v[j*2+1] = cv ? v1 : -1e4f;
            }
            float m = v[0];
            #pragma unroll
            for(int q=1;q<8;q++) m = fmaxf(m, v[q]);
            m = fmaxf(m, __shfl_xor_sync(0xFFFFFFFFu, m, 1));
            m = fmaxf(m, __shfl_xor_sync(0xFFFFFFFFu, m, 2));
            uint32_t eTh[4];
            float st=0.f, se=0.f, te=0.f;
            #pragma unroll
            for(int q=0;q<8;q+=2){
                float g0 = CTL2 * (v[q]   - m);
                float g1 = CTL2 * (v[q+1] - m);
                uint32_t eu = ex2_h2(g0, g1);
                eTh[q>>1] = eu;
                __half2 eh2 = *(__half2*)&eu;
                float2 ef = __half22float2(eh2);
                st += ef.x + ef.y;
                float e7a = pow7(ef.x), e7b = pow7(ef.y);
                se += e7a + e7b;
                te += e7a*(CL7*g0) + e7b*(CL7*g1);
            }
            if(rok){
                __half* erow = g_eT + (size_t)row * KTOT;
                #pragma unroll
                for(int j=0;j<4;j++){
                    int col = colBase + wn + j*8 + (lane & 3)*2;
                    if(col < KTOT)
                        __stcs((unsigned int*)(erow + col), eTh[j]);
                }
            }
            st += __shfl_xor_sync(0xFFFFFFFFu, st, 1);
            st += __shfl_xor_sync(0xFFFFFFFFu, st, 2);
            se += __shfl_xor_sync(0xFFFFFFFFu, se, 1);
            se += __shfl_xor_sync(0xFFFFFFFFu, se, 2);
            te += __shfl_xor_sync(0xFFFFFFFFu, te, 1);
            te += __shfl_xor_sync(0xFFFFFFFFu, te, 2);
            unsigned long long key =
                (((unsigned long long)fsort(best)) << 32) |
                (unsigned long long)(0xFFFFFFFFu - (unsigned)bc);
            {
                unsigned long long o1 = __shfl_xor_sync(0xFFFFFFFFu, key, 1);
                if(o1 > key) key = o1;
                unsigned long long o2 = __shfl_xor_sync(0xFFFFFFFFu, key, 2);
                if(o2 > key) key = o2;
            }
            if((lane & 3) == 0 && rok){
                size_t slotIdx = (size_t)row*NSLOT + blockIdx.x*4 + (w>>1);
                float4 p4; p4.x = m; p4.y = st; p4.z = se; p4.w = te;
                g_part[slotIdx] = p4;
                g_sidx[slotIdx] = 0xFFFFFFFFu - (unsigned)(key & 0xFFFFFFFFull);
            }
        }
    }
}

// ------------- K3: combine partials + scale factors + exact argmax repair -----
__global__ void combine(){
    int t = threadIdx.x;
    int row = blockIdx.x*8 + (t>>5);
    int lane = t & 31;
    if(row >= NTOT) return;
    const float4* P = g_part + (size_t)row*NSLOT;
    float m = -1e30f, st = 0.f, se = 0.f, te = 0.f;
    for(int s=lane; s<NSLOT; s+=32){
        float4 p = P[s];
        float M = fmaxf(m, p.x);
        float ca = __expf(CT*(m - M));
        float cb = __expf(CT*(p.x - M));
        float ca7 = pow7(ca), cb7 = pow7(cb);
        st = st*ca + p.y*cb;
        te = (te + CE*(m - M)*se)*ca7 + (p.w + CE*(p.x - M)*p.z)*cb7;
        se = se*ca7 + p.z*cb7;
        m = M;
    }
    #pragma unroll
    for(int off=16; off; off>>=1){
        float om  = __shfl_xor_sync(0xFFFFFFFFu, m,  off);
        float ost = __shfl_xor_sync(0xFFFFFFFFu, st, off);
        float ose = __shfl_xor_sync(0xFFFFFFFFu, se, off);
        float ote = __shfl_xor_sync(0xFFFFFFFFu, te, off);
        float M = fmaxf(m, om);
        float ca = __expf(CT*(m - M));
        float cb = __expf(CT*(om - M));
        float ca7 = pow7(ca), cb7 = pow7(cb);
        st = st*ca + ost*cb;
        te = (te + CE*(m - M)*se)*ca7 + (ote + CE*(om - M)*ose)*cb7;
        se = se*ca7 + ose*cb7;
        m = M;
    }
    float ist = 1.f / st, ise = 1.f / se;
    for(int s=lane; s<NSLOT; s+=32){
        float ms = P[s].x;
        float eT = __expf(CT*(ms - m));
        g_fT[(size_t)row*NSLOT + s] = eT * ist;
        g_fE[(size_t)row*NSLOT + s] = pow7(eT) * ise;
    }
    float thr = m - 3e-4f;
    float bestVal = -1e30f; int bestCol = 0x7FFFFFFF;
    const float4* zr = (const float4*)(g_zn32 + (size_t)row*MIDD);
    for(int s0=0; s0<NSLOT; s0+=32){
        int s = s0 + lane;
        bool c = (s < NSLOT) && (P[s].x >= thr);
        unsigned mk = __ballot_sync(0xFFFFFFFFu, c);
        while(mk){
            int src = __ffs(mk) - 1; mk &= mk - 1;
            int slot = s0 + src;
            int col = (int)g_sidx[(size_t)row*NSLOT + slot];
            float a = 0.f;
            const float4* er = (const float4*)(g_en + (size_t)col*MIDD);
            #pragma unroll 2
            for(int q=lane; q<64; q+=32){
                float4 av = zr[q], bv = er[q];
                a += av.x*bv.x + av.y*bv.y + av.z*bv.z + av.w*bv.w;
            }
            a = warpReduceSum(a);
            if(a > bestVal || (a == bestVal && col < bestCol)){
                bestVal = a; bestCol = col;
            }
        }
    }
    if(lane == 0){
        g_idx[row] = bestCol;
        g_occ[bestCol] = 1;
        atomicAdd(&g_acc[0], 2.f - 2.f*bestVal);
        atomicAdd(&g_acc[1], te/se - logf(se));
    }
}

// ------------- K4: probs + entropy column sums (streaming loads/stores) -------
__global__ void probs_avg(float* __restrict__ Cc){
    int k8 = blockIdx.x*256 + threadIdx.x;
    if(k8 >= KV8) return;
    int slot = k8 >> 2;
    int n0 = blockIdx.y * 50;
    float a[8];
    #pragma unroll
    for(int q=0;q<8;q++) a[q] = 0.f;
    const uint4* E = (const uint4*)g_eT;
    for(int n=n0; n<n0+50; n++){
        float fT = g_fT[(size_t)n*NSLOT + slot];
        float fE = g_fE[(size_t)n*NSLOT + slot];
        uint4 ev = __ldcs(&E[(size_t)n*KV8 + k8]);
        float2 f0 = __half22float2(*(__half2*)&ev.x);
        float2 f1 = __half22float2(*(__half2*)&ev.y);
        float2 f2 = __half22float2(*(__half2*)&ev.z);
        float2 f3 = __half22float2(*(__half2*)&ev.w);
        float vv[8] = {f0.x,f0.y,f1.x,f1.y,f2.x,f2.y,f3.x,f3.y};
        float4 o0, o1;
        o0.x = vv[0]*fT; o0.y = vv[1]*fT; o0.z = vv[2]*fT; o0.w = vv[3]*fT;
        o1.x = vv[4]*fT; o1.y = vv[5]*fT; o1.z = vv[6]*fT; o1.w = vv[7]*fT;
        #pragma unroll
        for(int q=0;q<8;q++) a[q] += pow7(vv[q]) * fE;
        size_t off = (size_t)n * KTOT + (size_t)k8*8;
        __stcs((float4*)(Cc + off),     o0);
        __stcs((float4*)(Cc + off + 4), o1);
    }
    int k = k8*8;
    #pragma unroll
    for(int q=0;q<8;q++) atomicAdd(&g_avgp[k+q], a[q]);
}

// ------------- K5: scalars -------------
__global__ void finalize(float* __restrict__ scal){
    int t = threadIdx.x;
    float cnt = 0.f, s = 0.f;
    for(int k=t; k<KTOT; k+=256){
        cnt += g_occ[k] ? 1.f : 0.f;
        float ap = g_avgp[k] * (1.f/7200.f);
        s += ap * logf(ap + 1e-5f);
    }
    cnt = warpReduceSum(cnt); s = warpReduceSum(s);
    __shared__ float r0[8], r1[8];
    if((t & 31) == 0){ r0[t>>5]=cnt; r1[t>>5]=s; }
    __syncthreads();
    if(t == 0){
        float c=0.f, sl=0.f;
        #pragma unroll
        for(int i=0;i<8;i++){ c+=r0[i]; sl+=r1[i]; }
        float usage = c / (float)KTOT;
        float vq = g_acc[0] / (7200.f * 256.f);
        float sample_entropy = -(g_acc[1] / 7200.f);
        scal[0] = usage;
        scal[1] = vq;
        scal[2] = vq;
        scal[3] = sample_entropy + sl;
    }
}

// ------------- K6: gather z_q_ste -------------
__global__ void gather_zq(float* __restrict__ outz){
    int n = blockIdx.x, m = threadIdx.x;
    outz[(size_t)n*MIDD + m] = g_en[(size_t)g_idx[n]*MIDD + m];
}

// ------------- launch -------------
extern "C" void kernel_launch(void* const* d_in, const int* in_sizes, int n_in,
                              void* d_out, int out_size){
    const float* x   = (const float*)d_in[0];
    const float* W   = (const float*)d_in[1];
    const float* b   = (const float*)d_in[2];
    const float* emb = (const float*)d_in[3];
    float* out = (float*)d_out;
    float* zq = out;
    float* probs = out + (size_t)NTOT*MIDD;
    float* scal  = out + (size_t)NTOT*MIDD + (size_t)NTOT*KTOT;

    cudaFuncSetAttribute(gemm_mma, cudaFuncAttributeMaxDynamicSharedMemorySize, 3*GSTG);
    cudaFuncSetAttribute(dp_mma,   cudaFuncAttributeMaxDynamicSharedMemorySize, 4*DPSTG);

    norm_emb<<<KTOT, 256>>>(emb);
    split_x<<<(NTOT*CIN/4 + 255)/256, 256>>>(x);
    split_wt<<<dim3(CIN/64, MIDD/64), 256>>>(W);
    dp_mma<<<NPAD/64, 256, 4*DPSTG>>>(b);
    gemm_mma<<<dim3(KPAD/128, NPAD/128), 256, 3*GSTG>>>();
    combine<<<NTOT/8, 256>>>();
    probs_avg<<<dim3((KV8+255)/256, 144), 256>>>(probs);
    finalize<<<1, 256>>>(scal);
    gather_zq<<<NTOT, 256>>>(zq);
}